// round 1
// baseline (speedup 1.0000x reference)
#include <cuda_runtime.h>
#include <math.h>

#define Bsz 8
#define Ssz 1024
#define Csz 512
#define Hsz 8
#define DHsz 64
#define Mtot (Bsz * Ssz)   // 8192

// Scratch (allocation-free rule: __device__ globals)
__device__ float g_q[Mtot * Csz];
__device__ float g_k[Mtot * Csz];
__device__ float g_v[Mtot * Csz];
__device__ float g_ctx[Mtot * Csz];

// ---------------------------------------------------------------------------
// Tiled fp32 GEMM:  out[m][n] = sum_c x[m][c] * W[n][c] + bias[n] (+ skip)
// BM=BN=64, BK=16, 256 threads, 4x4 micro-tile per thread.
// MODE: 0 -> g_q, 1 -> g_k, 2 -> g_v, 3 -> out_param (+skip)
// ---------------------------------------------------------------------------
template <int MODE>
__global__ __launch_bounds__(256)
void gemm_kernel(const float* __restrict__ x,
                 const float* __restrict__ W,
                 const float* __restrict__ bias,
                 const float* __restrict__ skip,
                 float* __restrict__ out_param) {
    constexpr int BM = 64, BN = 64, BK = 16;

    __shared__ float As[BM][BK + 1];   // As[m][k]
    __shared__ float Bs[BK][BN + 1];   // Bs[k][n]  (pad 65: conflict-free store)

    float* out;
    if (MODE == 0)      out = g_q;
    else if (MODE == 1) out = g_k;
    else if (MODE == 2) out = g_v;
    else                out = out_param;

    const int tid = threadIdx.x;
    const int tx = tid & 15;        // 0..15
    const int ty = tid >> 4;        // 0..15
    const int m0 = blockIdx.y * BM;
    const int n0 = blockIdx.x * BN;

    float acc[4][4];
#pragma unroll
    for (int i = 0; i < 4; ++i)
#pragma unroll
        for (int j = 0; j < 4; ++j) acc[i][j] = 0.f;

    for (int k0 = 0; k0 < Csz; k0 += BK) {
        // Load A tile: x[m0+m][k0+kk]
#pragma unroll
        for (int it = 0; it < 4; ++it) {
            int m = (tid >> 4) + it * 16;
            int kk = tid & 15;
            As[m][kk] = x[(m0 + m) * Csz + k0 + kk];
            Bs[kk][m] = W[(n0 + m) * Csz + k0 + kk];   // reuse m as n index
        }
        __syncthreads();

#pragma unroll
        for (int kk = 0; kk < BK; ++kk) {
            float ra[4], rb[4];
#pragma unroll
            for (int i = 0; i < 4; ++i) ra[i] = As[ty + 16 * i][kk];
#pragma unroll
            for (int j = 0; j < 4; ++j) rb[j] = Bs[kk][tx + 16 * j];
#pragma unroll
            for (int i = 0; i < 4; ++i)
#pragma unroll
                for (int j = 0; j < 4; ++j)
                    acc[i][j] = fmaf(ra[i], rb[j], acc[i][j]);
        }
        __syncthreads();
    }

#pragma unroll
    for (int i = 0; i < 4; ++i) {
        int m = m0 + ty + 16 * i;
#pragma unroll
        for (int j = 0; j < 4; ++j) {
            int n = n0 + tx + 16 * j;
            float v = acc[i][j] + bias[n];
            if (MODE == 3) v += skip[m * Csz + n];
            out[m * Csz + n] = v;
        }
    }
}

// ---------------------------------------------------------------------------
// Flash-style attention: one CTA per (q-tile of 64, head, batch).
// Scores in registers, online softmax via shuffles, P staged via smem for PV.
// Dynamic smem: Qs[64][64] + KV[64][65] + Ps[64][64]  = 49,408 bytes.
// ---------------------------------------------------------------------------
__global__ __launch_bounds__(256)
void attn_kernel() {
    extern __shared__ float sm[];
    float* Qs = sm;                       // [64][64]
    float* KV = sm + 64 * 64;             // [64][65]
    float* Ps = sm + 64 * 64 + 64 * 65;   // [64][64]

    const int qt = blockIdx.x;            // 0..15
    const int h  = blockIdx.y;            // 0..7
    const int b  = blockIdx.z;            // 0..7
    const int s0 = qt * 64;
    const int tid = threadIdx.x;
    const int tx = tid & 15;
    const int ty = tid >> 4;

    const float scale = 0.125f;           // 1/sqrt(64)
    const int base = (b * Ssz) * Csz + h * DHsz;

    // Load Q tile (scaled)
#pragma unroll
    for (int it = 0; it < 16; ++it) {
        int e = tid + it * 256;           // 0..4095
        int r = e >> 6, d = e & 63;
        Qs[r * 64 + d] = g_q[base + (s0 + r) * Csz + d] * scale;
    }

    float m_i[4], l_i[4], o[4][4];
#pragma unroll
    for (int i = 0; i < 4; ++i) {
        m_i[i] = -INFINITY;
        l_i[i] = 0.f;
#pragma unroll
        for (int j = 0; j < 4; ++j) o[i][j] = 0.f;
    }
    __syncthreads();

    for (int kt = 0; kt < 16; ++kt) {
        const int k0 = kt * 64;

        // Load K tile -> KV [key][d], pad 65
#pragma unroll
        for (int it = 0; it < 16; ++it) {
            int e = tid + it * 256;
            int r = e >> 6, d = e & 63;
            KV[r * 65 + d] = g_k[base + (k0 + r) * Csz + d];
        }
        __syncthreads();

        // Scores: sc[i][j] = Q[ty+16i][:] . K[tx+16j][:]
        float sc[4][4];
#pragma unroll
        for (int i = 0; i < 4; ++i)
#pragma unroll
            for (int j = 0; j < 4; ++j) sc[i][j] = 0.f;

#pragma unroll 8
        for (int d = 0; d < 64; ++d) {
            float ra[4], rb[4];
#pragma unroll
            for (int i = 0; i < 4; ++i) ra[i] = Qs[(ty + 16 * i) * 64 + d];
#pragma unroll
            for (int j = 0; j < 4; ++j) rb[j] = KV[(tx + 16 * j) * 65 + d];
#pragma unroll
            for (int i = 0; i < 4; ++i)
#pragma unroll
                for (int j = 0; j < 4; ++j)
                    sc[i][j] = fmaf(ra[i], rb[j], sc[i][j]);
        }

        // Online softmax (row = ty+16i, spread over 16 tx lanes)
#pragma unroll
        for (int i = 0; i < 4; ++i) {
            float tm = sc[i][0];
#pragma unroll
            for (int j = 1; j < 4; ++j) tm = fmaxf(tm, sc[i][j]);
            tm = fmaxf(tm, __shfl_xor_sync(0xffffffffu, tm, 1));
            tm = fmaxf(tm, __shfl_xor_sync(0xffffffffu, tm, 2));
            tm = fmaxf(tm, __shfl_xor_sync(0xffffffffu, tm, 4));
            tm = fmaxf(tm, __shfl_xor_sync(0xffffffffu, tm, 8));

            float mn = fmaxf(m_i[i], tm);
            float alpha = __expf(m_i[i] - mn);   // exp(-inf)=0 first iter
            m_i[i] = mn;

            float ps = 0.f;
#pragma unroll
            for (int j = 0; j < 4; ++j) {
                sc[i][j] = __expf(sc[i][j] - mn);
                ps += sc[i][j];
            }
            ps += __shfl_xor_sync(0xffffffffu, ps, 1);
            ps += __shfl_xor_sync(0xffffffffu, ps, 2);
            ps += __shfl_xor_sync(0xffffffffu, ps, 4);
            ps += __shfl_xor_sync(0xffffffffu, ps, 8);

            l_i[i] = l_i[i] * alpha + ps;
#pragma unroll
            for (int j = 0; j < 4; ++j) o[i][j] *= alpha;

            // Stage P
#pragma unroll
            for (int j = 0; j < 4; ++j)
                Ps[(ty + 16 * i) * 64 + tx + 16 * j] = sc[i][j];
        }
        __syncthreads();   // Ps complete; everyone done reading KV-as-K

        // Load V tile -> KV [key][d]
#pragma unroll
        for (int it = 0; it < 16; ++it) {
            int e = tid + it * 256;
            int r = e >> 6, d = e & 63;
            KV[r * 65 + d] = g_v[base + (k0 + r) * Csz + d];
        }
        __syncthreads();

        // PV: o[i][j] += P[ty+16i][kk] * V[kk][tx+16j]
#pragma unroll 8
        for (int kk = 0; kk < 64; ++kk) {
            float ra[4], rb[4];
#pragma unroll
            for (int i = 0; i < 4; ++i) ra[i] = Ps[(ty + 16 * i) * 64 + kk];
#pragma unroll
            for (int j = 0; j < 4; ++j) rb[j] = KV[kk * 65 + tx + 16 * j];
#pragma unroll
            for (int i = 0; i < 4; ++i)
#pragma unroll
                for (int j = 0; j < 4; ++j)
                    o[i][j] = fmaf(ra[i], rb[j], o[i][j]);
        }
        __syncthreads();   // before next iter overwrites KV / Ps
    }

    // Epilogue: normalize, write ctx[b][s][h*64+d]
#pragma unroll
    for (int i = 0; i < 4; ++i) {
        float inv_l = 1.0f / l_i[i];
        int s = s0 + ty + 16 * i;
#pragma unroll
        for (int j = 0; j < 4; ++j) {
            int d = tx + 16 * j;
            g_ctx[(b * Ssz + s) * Csz + h * DHsz + d] = o[i][j] * inv_l;
        }
    }
}

// ---------------------------------------------------------------------------
// Launch
// ---------------------------------------------------------------------------
extern "C" void kernel_launch(void* const* d_in, const int* in_sizes, int n_in,
                              void* d_out, int out_size) {
    const float* x    = (const float*)d_in[0];
    const float* skip = (const float*)d_in[1];
    const float* Wq   = (const float*)d_in[2];
    const float* bq   = (const float*)d_in[3];
    const float* Wk   = (const float*)d_in[4];
    const float* bk   = (const float*)d_in[5];
    const float* Wv   = (const float*)d_in[6];
    const float* bv   = (const float*)d_in[7];
    const float* Wo   = (const float*)d_in[8];
    const float* bo   = (const float*)d_in[9];
    float* out = (float*)d_out;

    dim3 gblk(256);
    dim3 ggrid(Csz / 64, Mtot / 64);   // (8, 128)

    gemm_kernel<0><<<ggrid, gblk>>>(x, Wq, bq, nullptr, nullptr);
    gemm_kernel<1><<<ggrid, gblk>>>(x, Wk, bk, nullptr, nullptr);
    gemm_kernel<2><<<ggrid, gblk>>>(x, Wv, bv, nullptr, nullptr);

    const int attn_smem = (64 * 64 + 64 * 65 + 64 * 64) * (int)sizeof(float);
    cudaFuncSetAttribute(attn_kernel, cudaFuncAttributeMaxDynamicSharedMemorySize,
                         attn_smem);
    dim3 agrid(Ssz / 64, Hsz, Bsz);    // (16, 8, 8)
    attn_kernel<<<agrid, 256, attn_smem>>>();

    // ctx is a __device__ global: pass via symbol-resident access inside kernel.
    // gemm_kernel<3> reads ctx through a pointer; fetch its device address.
    void* ctx_ptr = nullptr;
    cudaGetSymbolAddress(&ctx_ptr, g_ctx);
    gemm_kernel<3><<<ggrid, gblk>>>((const float*)ctx_ptr, Wo, bo, skip, out);
}

// round 4
// speedup vs baseline: 3.5540x; 3.5540x over previous
#include <cuda_runtime.h>
#include <cstdint>
#include <math.h>

#define Bsz 8
#define Ssz 1024
#define Csz 512
#define Hsz 8
#define DHsz 64
#define Mtot (Bsz * Ssz)   // 8192

// ---------------------------------------------------------------------------
// Scratch (__device__ globals; no allocation allowed)
// ---------------------------------------------------------------------------
__device__ float g_q[Mtot * Csz];
__device__ float g_k[Mtot * Csz];
__device__ float g_v[Mtot * Csz];
__device__ float g_ctx[Mtot * Csz];

// ---------------------------------------------------------------------------
// tf32 helpers (sm_80+ generic — NOT arch-'a' gated)
// ---------------------------------------------------------------------------
__device__ __forceinline__ uint32_t f2tf32(float f) {
    uint32_t r;
    asm("cvt.rna.tf32.f32 %0, %1;" : "=r"(r) : "f"(f));
    return r;
}

// D += A*B, m16n8k8 tf32. c[4] fp32, a[4], b[2] tf32 bits.
__device__ __forceinline__ void mma_tf32(float* c, const uint32_t* a,
                                         const uint32_t* b) {
    asm volatile(
        "mma.sync.aligned.m16n8k8.row.col.f32.tf32.tf32.f32 "
        "{%0,%1,%2,%3}, {%4,%5,%6,%7}, {%8,%9}, {%0,%1,%2,%3};"
        : "+f"(c[0]), "+f"(c[1]), "+f"(c[2]), "+f"(c[3])
        : "r"(a[0]), "r"(a[1]), "r"(a[2]), "r"(a[3]), "r"(b[0]), "r"(b[1]));
}

// ---------------------------------------------------------------------------
// tf32 GEMM:  out[m][n] = sum_c x[m][c] * W[n][c] + bias[n] (+ skip)
// BM=BN=128, BK=32. 256 threads / 8 warps, warp tile 64x32.
// MODE: 0 -> g_q, 1 -> g_k, 2 -> g_v, 3 -> out_param (+skip)
// ---------------------------------------------------------------------------
template <int MODE>
__global__ __launch_bounds__(256)
void gemm_tc(const float* __restrict__ x, const float* __restrict__ W,
             const float* __restrict__ bias, const float* __restrict__ skip,
             float* __restrict__ out_param) {
    __shared__ uint32_t As[128][36];   // [m][k] stride 36: bank=4*row+col
    __shared__ uint32_t Bs[128][36];   // [n][k]

    float* out;
    if (MODE == 0)      out = g_q;
    else if (MODE == 1) out = g_k;
    else if (MODE == 2) out = g_v;
    else                out = out_param;

    const int tid = threadIdx.x, lane = tid & 31, wid = tid >> 5;
    const int wm = (wid >> 2) * 64;      // 0 / 64
    const int wn = (wid & 3) * 32;       // 0 / 32 / 64 / 96
    const int m0 = blockIdx.y * 128;
    const int n0 = blockIdx.x * 128;

    float acc[4][4][4];
#pragma unroll
    for (int mt = 0; mt < 4; ++mt)
#pragma unroll
        for (int nt = 0; nt < 4; ++nt)
#pragma unroll
            for (int r = 0; r < 4; ++r) acc[mt][nt][r] = 0.f;

    for (int k0 = 0; k0 < Csz; k0 += 32) {
        // Stage tiles: 128 rows x 32 cols fp32 -> tf32 bits in smem.
#pragma unroll
        for (int i = 0; i < 4; ++i) {
            int e = tid + i * 256;       // 0..1023
            int r = e >> 3, c4 = e & 7;  // row, float4-col
            float4 va = *(const float4*)&x[(size_t)(m0 + r) * Csz + k0 + c4 * 4];
            As[r][c4 * 4 + 0] = f2tf32(va.x);
            As[r][c4 * 4 + 1] = f2tf32(va.y);
            As[r][c4 * 4 + 2] = f2tf32(va.z);
            As[r][c4 * 4 + 3] = f2tf32(va.w);
            float4 vb = *(const float4*)&W[(size_t)(n0 + r) * Csz + k0 + c4 * 4];
            Bs[r][c4 * 4 + 0] = f2tf32(vb.x);
            Bs[r][c4 * 4 + 1] = f2tf32(vb.y);
            Bs[r][c4 * 4 + 2] = f2tf32(vb.z);
            Bs[r][c4 * 4 + 3] = f2tf32(vb.w);
        }
        __syncthreads();

#pragma unroll
        for (int ks = 0; ks < 4; ++ks) {
            const int kc = ks * 8 + (lane & 3);
            uint32_t af[4][4], bf[4][2];
            const int ar = wm + (lane >> 2);
#pragma unroll
            for (int mt = 0; mt < 4; ++mt) {
                af[mt][0] = As[ar + mt * 16][kc];
                af[mt][1] = As[ar + mt * 16 + 8][kc];
                af[mt][2] = As[ar + mt * 16][kc + 4];
                af[mt][3] = As[ar + mt * 16 + 8][kc + 4];
            }
            const int br = wn + (lane >> 2);
#pragma unroll
            for (int nt = 0; nt < 4; ++nt) {
                bf[nt][0] = Bs[br + nt * 8][kc];
                bf[nt][1] = Bs[br + nt * 8][kc + 4];
            }
#pragma unroll
            for (int mt = 0; mt < 4; ++mt)
#pragma unroll
                for (int nt = 0; nt < 4; ++nt)
                    mma_tf32(acc[mt][nt], af[mt], bf[nt]);
        }
        __syncthreads();
    }

    // Epilogue
#pragma unroll
    for (int mt = 0; mt < 4; ++mt) {
        const int r0 = m0 + wm + mt * 16 + (lane >> 2);
#pragma unroll
        for (int nt = 0; nt < 4; ++nt) {
            const int c = n0 + wn + nt * 8 + (lane & 3) * 2;
            float b0 = bias[c], b1 = bias[c + 1];
            float2 v0 = make_float2(acc[mt][nt][0] + b0, acc[mt][nt][1] + b1);
            float2 v1 = make_float2(acc[mt][nt][2] + b0, acc[mt][nt][3] + b1);
            if (MODE == 3) {
                const float* s0p = &skip[(size_t)r0 * Csz + c];
                const float* s1p = &skip[(size_t)(r0 + 8) * Csz + c];
                v0.x += s0p[0]; v0.y += s0p[1];
                v1.x += s1p[0]; v1.y += s1p[1];
            }
            *(float2*)&out[(size_t)r0 * Csz + c] = v0;
            *(float2*)&out[(size_t)(r0 + 8) * Csz + c] = v1;
        }
    }
}

// ---------------------------------------------------------------------------
// Flash attention, tf32 tensor cores.
// CTA: 256 threads / 8 warps; q-tile 128, key-tile 64, DH=64.
// Warp w owns q-rows [w*16, w*16+16) x all 64 keys -> softmax rows stay in-quad.
// Smem strides: Qs/Ks/Ps 68 (bank=4r+c), Vs 72 (bank=8r+c) — conflict-free frags.
// ---------------------------------------------------------------------------
#define QS_STR 68
#define KS_STR 68
#define VS_STR 72
#define PS_STR 68
#define ATTN_SMEM ((128 * QS_STR + 64 * KS_STR + 64 * VS_STR + 128 * PS_STR) * 4)

__global__ __launch_bounds__(256)
void attn_tc() {
    extern __shared__ uint32_t sm[];
    uint32_t* Qs = sm;                         // [128][68]
    uint32_t* Ks = Qs + 128 * QS_STR;          // [64][68]
    uint32_t* Vs = Ks + 64 * KS_STR;           // [64][72]
    uint32_t* Ps = Vs + 64 * VS_STR;           // [128][68]

    const int qt = blockIdx.x, h = blockIdx.y, b = blockIdx.z;
    const int s0 = qt * 128;
    const int tid = threadIdx.x, lane = tid & 31, wid = tid >> 5;
    const size_t base = ((size_t)b * Ssz) * Csz + h * DHsz;

    // Load Q tile (pre-scaled by 1/sqrt(DH), tf32-rounded).
#pragma unroll
    for (int i = 0; i < 8; ++i) {
        int e = tid + i * 256;        // 0..2047 float4s
        int r = e >> 4, c4 = e & 15;
        float4 v = *(const float4*)&g_q[base + (size_t)(s0 + r) * Csz + c4 * 4];
        Qs[r * QS_STR + c4 * 4 + 0] = f2tf32(v.x * 0.125f);
        Qs[r * QS_STR + c4 * 4 + 1] = f2tf32(v.y * 0.125f);
        Qs[r * QS_STR + c4 * 4 + 2] = f2tf32(v.z * 0.125f);
        Qs[r * QS_STR + c4 * 4 + 3] = f2tf32(v.w * 0.125f);
    }

    float m_i[2] = {-INFINITY, -INFINITY};
    float l_i[2] = {0.f, 0.f};
    float o[8][4];
#pragma unroll
    for (int nt = 0; nt < 8; ++nt)
#pragma unroll
        for (int r = 0; r < 4; ++r) o[nt][r] = 0.f;

    __syncthreads();

    for (int kt = 0; kt < 16; ++kt) {
        const int k0 = kt * 64;
        // Load K, V tiles (64x64 each).
#pragma unroll
        for (int i = 0; i < 4; ++i) {
            int e = tid + i * 256;     // 0..1023 float4s
            int r = e >> 4, c4 = e & 15;
            float4 vk = *(const float4*)&g_k[base + (size_t)(k0 + r) * Csz + c4 * 4];
            Ks[r * KS_STR + c4 * 4 + 0] = f2tf32(vk.x);
            Ks[r * KS_STR + c4 * 4 + 1] = f2tf32(vk.y);
            Ks[r * KS_STR + c4 * 4 + 2] = f2tf32(vk.z);
            Ks[r * KS_STR + c4 * 4 + 3] = f2tf32(vk.w);
            float4 vv = *(const float4*)&g_v[base + (size_t)(k0 + r) * Csz + c4 * 4];
            Vs[r * VS_STR + c4 * 4 + 0] = f2tf32(vv.x);
            Vs[r * VS_STR + c4 * 4 + 1] = f2tf32(vv.y);
            Vs[r * VS_STR + c4 * 4 + 2] = f2tf32(vv.z);
            Vs[r * VS_STR + c4 * 4 + 3] = f2tf32(vv.w);
        }
        __syncthreads();

        // S = Q K^T : warp computes rows [wid*16, +16) x 64 keys.
        float s[8][4];
#pragma unroll
        for (int nt = 0; nt < 8; ++nt)
#pragma unroll
            for (int r = 0; r < 4; ++r) s[nt][r] = 0.f;

#pragma unroll
        for (int ks = 0; ks < 8; ++ks) {
            const int d0 = ks * 8 + (lane & 3);
            const int ar = wid * 16 + (lane >> 2);
            uint32_t af[4];
            af[0] = Qs[ar * QS_STR + d0];
            af[1] = Qs[(ar + 8) * QS_STR + d0];
            af[2] = Qs[ar * QS_STR + d0 + 4];
            af[3] = Qs[(ar + 8) * QS_STR + d0 + 4];
#pragma unroll
            for (int nt = 0; nt < 8; ++nt) {
                const int key = nt * 8 + (lane >> 2);
                uint32_t bf[2];
                bf[0] = Ks[key * KS_STR + d0];
                bf[1] = Ks[key * KS_STR + d0 + 4];
                mma_tf32(s[nt], af, bf);
            }
        }

        // Online softmax; thread holds rows r0=wid*16+lane/4 and r0+8,
        // 16 cols each (nt*8 + (lane&3)*2 {,+1}); quad = lanes sharing row.
#pragma unroll
        for (int r = 0; r < 2; ++r) {
            float tm = -INFINITY;
#pragma unroll
            for (int nt = 0; nt < 8; ++nt)
                tm = fmaxf(tm, fmaxf(s[nt][2 * r], s[nt][2 * r + 1]));
            tm = fmaxf(tm, __shfl_xor_sync(0xffffffffu, tm, 1));
            tm = fmaxf(tm, __shfl_xor_sync(0xffffffffu, tm, 2));

            float mn = fmaxf(m_i[r], tm);
            float alpha = __expf(m_i[r] - mn);
            m_i[r] = mn;

            float ps = 0.f;
#pragma unroll
            for (int nt = 0; nt < 8; ++nt) {
                s[nt][2 * r]     = __expf(s[nt][2 * r] - mn);
                s[nt][2 * r + 1] = __expf(s[nt][2 * r + 1] - mn);
                ps += s[nt][2 * r] + s[nt][2 * r + 1];
            }
            ps += __shfl_xor_sync(0xffffffffu, ps, 1);
            ps += __shfl_xor_sync(0xffffffffu, ps, 2);

            l_i[r] = l_i[r] * alpha + ps;
#pragma unroll
            for (int nt = 0; nt < 8; ++nt) {
                o[nt][2 * r]     *= alpha;
                o[nt][2 * r + 1] *= alpha;
            }
        }

        // Stage P (tf32) — warp-private rows, so only __syncwarp needed.
        {
            const int r0 = wid * 16 + (lane >> 2);
#pragma unroll
            for (int nt = 0; nt < 8; ++nt) {
                const int c = nt * 8 + (lane & 3) * 2;
                Ps[r0 * PS_STR + c]           = f2tf32(s[nt][0]);
                Ps[r0 * PS_STR + c + 1]       = f2tf32(s[nt][1]);
                Ps[(r0 + 8) * PS_STR + c]     = f2tf32(s[nt][2]);
                Ps[(r0 + 8) * PS_STR + c + 1] = f2tf32(s[nt][3]);
            }
        }
        __syncwarp();

        // O += P V : k-dim = keys (64), n = d (64).
#pragma unroll
        for (int ks = 0; ks < 8; ++ks) {
            const int kk = ks * 8 + (lane & 3);
            const int ar = wid * 16 + (lane >> 2);
            uint32_t af[4];
            af[0] = Ps[ar * PS_STR + kk];
            af[1] = Ps[(ar + 8) * PS_STR + kk];
            af[2] = Ps[ar * PS_STR + kk + 4];
            af[3] = Ps[(ar + 8) * PS_STR + kk + 4];
#pragma unroll
            for (int nt = 0; nt < 8; ++nt) {
                const int dd = nt * 8 + (lane >> 2);
                uint32_t bf[2];
                bf[0] = Vs[kk * VS_STR + dd];
                bf[1] = Vs[(kk + 4) * VS_STR + dd];
                mma_tf32(o[nt], af, bf);
            }
        }
        __syncthreads();   // before next iter overwrites Ks/Vs
    }

    // Epilogue: normalize & store ctx[b][s][h*64+d].
#pragma unroll
    for (int r = 0; r < 2; ++r) {
        const float inv = 1.0f / l_i[r];
        const int row = s0 + wid * 16 + (lane >> 2) + r * 8;
#pragma unroll
        for (int nt = 0; nt < 8; ++nt) {
            const int dd = nt * 8 + (lane & 3) * 2;
            float2 v = make_float2(o[nt][2 * r] * inv, o[nt][2 * r + 1] * inv);
            *(float2*)&g_ctx[base + (size_t)row * Csz + dd] = v;
        }
    }
}

// ---------------------------------------------------------------------------
// Launch
// ---------------------------------------------------------------------------
extern "C" void kernel_launch(void* const* d_in, const int* in_sizes, int n_in,
                              void* d_out, int out_size) {
    const float* x    = (const float*)d_in[0];
    const float* skip = (const float*)d_in[1];
    const float* Wq   = (const float*)d_in[2];
    const float* bq   = (const float*)d_in[3];
    const float* Wk   = (const float*)d_in[4];
    const float* bk   = (const float*)d_in[5];
    const float* Wv   = (const float*)d_in[6];
    const float* bv   = (const float*)d_in[7];
    const float* Wo   = (const float*)d_in[8];
    const float* bo   = (const float*)d_in[9];
    float* out = (float*)d_out;

    void* p_ctx = nullptr;
    cudaGetSymbolAddress(&p_ctx, g_ctx);

    dim3 ggrid(Csz / 128, Mtot / 128);   // (4, 64)
    gemm_tc<0><<<ggrid, 256>>>(x, Wq, bq, nullptr, nullptr);
    gemm_tc<1><<<ggrid, 256>>>(x, Wk, bk, nullptr, nullptr);
    gemm_tc<2><<<ggrid, 256>>>(x, Wv, bv, nullptr, nullptr);

    cudaFuncSetAttribute(attn_tc, cudaFuncAttributeMaxDynamicSharedMemorySize,
                         ATTN_SMEM);
    dim3 agrid(Ssz / 128, Hsz, Bsz);     // (8, 8, 8)
    attn_tc<<<agrid, 256, ATTN_SMEM>>>();

    gemm_tc<3><<<ggrid, 256>>>((const float*)p_ctx, Wo, bo, skip, out);
}

// round 9
// speedup vs baseline: 5.0410x; 1.4184x over previous
#include <cuda_runtime.h>
#include <cuda_fp16.h>
#include <cstdint>
#include <math.h>

#define Bsz 8
#define Ssz 1024
#define Csz 512
#define Hsz 8
#define DHsz 64
#define Mtot (Bsz * Ssz)   // 8192

// ---------------------------------------------------------------------------
// Scratch (__device__ globals; no allocation allowed)
// ---------------------------------------------------------------------------
__device__ float g_q[Mtot * Csz];
__device__ float g_k[Mtot * Csz];
__device__ float g_v[Mtot * Csz];
__device__ float g_ctx[Mtot * Csz];

// ---------------------------------------------------------------------------
// fp16 helpers (sm_75+ generic mma.sync — NOT arch-'a' gated)
// ---------------------------------------------------------------------------
__device__ __forceinline__ uint32_t pack2h(float a, float b) {
    __half2 h = __floats2half2_rn(a, b);
    return *(uint32_t*)&h;
}

// D += A*B, m16n8k16 f16 in / f32 accum. c[4] fp32, a[4], b[2] packed half2.
__device__ __forceinline__ void mma_f16(float* c, const uint32_t* a,
                                        const uint32_t* b) {
    asm volatile(
        "mma.sync.aligned.m16n8k16.row.col.f32.f16.f16.f32 "
        "{%0,%1,%2,%3}, {%4,%5,%6,%7}, {%8,%9}, {%0,%1,%2,%3};"
        : "+f"(c[0]), "+f"(c[1]), "+f"(c[2]), "+f"(c[3])
        : "r"(a[0]), "r"(a[1]), "r"(a[2]), "r"(a[3]), "r"(b[0]), "r"(b[1]));
}

// ---------------------------------------------------------------------------
// fp16 GEMM core: out[m][n] = sum_c x[m][c] * W[n][c] + bias[n] (+ skip)
// BM=BN=128, BK=64 halves (32 u32/row). 256 threads / 8 warps, warp 64x32.
// smem stride 36 u32: fragment-load bank = 4r+c (conflict-free).
// ---------------------------------------------------------------------------
__device__ __forceinline__
void gemm_body(const float* __restrict__ x, const float* __restrict__ W,
               const float* __restrict__ bias, const float* __restrict__ skip,
               float* __restrict__ out, int m0, int n0) {
    __shared__ uint32_t As[128][36];
    __shared__ uint32_t Bs[128][36];

    const int tid = threadIdx.x, lane = tid & 31, wid = tid >> 5;
    const int wm = (wid >> 2) * 64;
    const int wn = (wid & 3) * 32;

    float acc[4][4][4];
#pragma unroll
    for (int mt = 0; mt < 4; ++mt)
#pragma unroll
        for (int nt = 0; nt < 4; ++nt)
#pragma unroll
            for (int r = 0; r < 4; ++r) acc[mt][nt][r] = 0.f;

    for (int k0 = 0; k0 < Csz; k0 += 64) {
        // Stage: 128 rows x 64 halves per array (2048 float4 each).
#pragma unroll
        for (int i = 0; i < 8; ++i) {
            int e = tid + i * 256;       // 0..2047
            int r = e >> 4, c4 = e & 15;
            float4 va = *(const float4*)&x[(size_t)(m0 + r) * Csz + k0 + c4 * 4];
            As[r][c4 * 2]     = pack2h(va.x, va.y);
            As[r][c4 * 2 + 1] = pack2h(va.z, va.w);
            float4 vb = *(const float4*)&W[(size_t)(n0 + r) * Csz + k0 + c4 * 4];
            Bs[r][c4 * 2]     = pack2h(vb.x, vb.y);
            Bs[r][c4 * 2 + 1] = pack2h(vb.z, vb.w);
        }
        __syncthreads();

#pragma unroll
        for (int ks = 0; ks < 4; ++ks) {         // 4 x K=16 steps
            const int kc = ks * 8 + (lane & 3);
            uint32_t af[4][4], bf[4][2];
            const int ar = wm + (lane >> 2);
#pragma unroll
            for (int mt = 0; mt < 4; ++mt) {
                af[mt][0] = As[ar + mt * 16][kc];
                af[mt][1] = As[ar + mt * 16 + 8][kc];
                af[mt][2] = As[ar + mt * 16][kc + 4];
                af[mt][3] = As[ar + mt * 16 + 8][kc + 4];
            }
            const int br = wn + (lane >> 2);
#pragma unroll
            for (int nt = 0; nt < 4; ++nt) {
                bf[nt][0] = Bs[br + nt * 8][kc];
                bf[nt][1] = Bs[br + nt * 8][kc + 4];
            }
#pragma unroll
            for (int mt = 0; mt < 4; ++mt)
#pragma unroll
                for (int nt = 0; nt < 4; ++nt)
                    mma_f16(acc[mt][nt], af[mt], bf[nt]);
        }
        __syncthreads();
    }

#pragma unroll
    for (int mt = 0; mt < 4; ++mt) {
        const int r0 = m0 + wm + mt * 16 + (lane >> 2);
#pragma unroll
        for (int nt = 0; nt < 4; ++nt) {
            const int c = n0 + wn + nt * 8 + (lane & 3) * 2;
            float b0 = bias[c], b1 = bias[c + 1];
            float2 v0 = make_float2(acc[mt][nt][0] + b0, acc[mt][nt][1] + b1);
            float2 v1 = make_float2(acc[mt][nt][2] + b0, acc[mt][nt][3] + b1);
            if (skip) {
                const float* s0p = &skip[(size_t)r0 * Csz + c];
                const float* s1p = &skip[(size_t)(r0 + 8) * Csz + c];
                v0.x += s0p[0]; v0.y += s0p[1];
                v1.x += s1p[0]; v1.y += s1p[1];
            }
            *(float2*)&out[(size_t)r0 * Csz + c] = v0;
            *(float2*)&out[(size_t)(r0 + 8) * Csz + c] = v1;
        }
    }
}

// Fused QKV: blockIdx.z picks projection (0=Q,1=K,2=V).
__global__ __launch_bounds__(256)
void qkv_gemm(const float* __restrict__ x,
              const float* __restrict__ Wq, const float* __restrict__ bq,
              const float* __restrict__ Wk, const float* __restrict__ bk,
              const float* __restrict__ Wv, const float* __restrict__ bv) {
    const float* W; const float* b; float* out;
    if (blockIdx.z == 0)      { W = Wq; b = bq; out = g_q; }
    else if (blockIdx.z == 1) { W = Wk; b = bk; out = g_k; }
    else                      { W = Wv; b = bv; out = g_v; }
    gemm_body(x, W, b, nullptr, out, blockIdx.y * 128, blockIdx.x * 128);
}

__global__ __launch_bounds__(256)
void o_gemm(const float* __restrict__ ctx, const float* __restrict__ Wo,
            const float* __restrict__ bo, const float* __restrict__ skip,
            float* __restrict__ out) {
    gemm_body(ctx, Wo, bo, skip, out, blockIdx.y * 128, blockIdx.x * 128);
}

// ---------------------------------------------------------------------------
// Flash attention, fp16 mma.sync, register-direct P.
// 256 threads / 8 warps; q-tile 128, key-tile 64, DH=64.
// Warp w owns q-rows [w*16, w*16+16); softmax rows live in a lane quad.
// Smem overlay: Qs[128][36] u32 == { Ks[64][36]; Vt[64][36] } (18,432 B).
// ---------------------------------------------------------------------------
__global__ __launch_bounds__(256)
void attn_tc() {
    __shared__ uint32_t smA[128 * 36];
    uint32_t* Qs = smA;                 // [128][36] during Q-frag extraction
    uint32_t* Ks = smA;                 // [64][36]
    uint32_t* Vt = smA + 64 * 36;       // [64][36]  (V transposed: [d][key])

    const int qt = blockIdx.x, h = blockIdx.y, b = blockIdx.z;
    const int s0 = qt * 128;
    const int tid = threadIdx.x, lane = tid & 31, wid = tid >> 5;
    const size_t base = ((size_t)b * Ssz) * Csz + h * DHsz;

    // --- Stage Q (scaled), extract per-warp fragments, then free the smem ---
#pragma unroll
    for (int i = 0; i < 8; ++i) {
        int e = tid + i * 256;          // 0..2047 float4s (128 x 16)
        int r = e >> 4, c4 = e & 15;
        float4 v = *(const float4*)&g_q[base + (size_t)(s0 + r) * Csz + c4 * 4];
        Qs[r * 36 + c4 * 2]     = pack2h(v.x * 0.125f, v.y * 0.125f);
        Qs[r * 36 + c4 * 2 + 1] = pack2h(v.z * 0.125f, v.w * 0.125f);
    }
    __syncthreads();

    uint32_t aq[4][4];                  // Q fragments for 4 K=16 steps
    {
        const int ar = wid * 16 + (lane >> 2);
#pragma unroll
        for (int ks = 0; ks < 4; ++ks) {
            const int kc = ks * 8 + (lane & 3);
            aq[ks][0] = Qs[ar * 36 + kc];
            aq[ks][1] = Qs[(ar + 8) * 36 + kc];
            aq[ks][2] = Qs[ar * 36 + kc + 4];
            aq[ks][3] = Qs[(ar + 8) * 36 + kc + 4];
        }
    }
    __syncthreads();                    // Qs region now reusable for K/V

    float m_i[2] = {-INFINITY, -INFINITY};
    float l_i[2] = {0.f, 0.f};
    float o[8][4];
#pragma unroll
    for (int nt = 0; nt < 8; ++nt)
#pragma unroll
        for (int r = 0; r < 4; ++r) o[nt][r] = 0.f;

    for (int kt = 0; kt < 16; ++kt) {
        const int k0 = kt * 64;

        // Stage K [key][d] (u32-packed halves).
#pragma unroll
        for (int i = 0; i < 4; ++i) {
            int e = tid + i * 256;      // 0..1023 float4s (64 x 16)
            int r = e >> 4, c4 = e & 15;
            float4 vk = *(const float4*)&g_k[base + (size_t)(k0 + r) * Csz + c4 * 4];
            Ks[r * 36 + c4 * 2]     = pack2h(vk.x, vk.y);
            Ks[r * 36 + c4 * 2 + 1] = pack2h(vk.z, vk.w);
        }
        // Stage V transposed: Vt[d][key] halves (row stride 72 halves).
        {
            __half* vth = (__half*)Vt;
            const int key = tid & 63;
#pragma unroll
            for (int i = 0; i < 4; ++i) {
                const int d4 = (tid >> 6) + i * 4;   // 0..15
                float4 vv = *(const float4*)&g_v[base + (size_t)(k0 + key) * Csz + d4 * 4];
                vth[(d4 * 4 + 0) * 72 + key] = __float2half_rn(vv.x);
                vth[(d4 * 4 + 1) * 72 + key] = __float2half_rn(vv.y);
                vth[(d4 * 4 + 2) * 72 + key] = __float2half_rn(vv.z);
                vth[(d4 * 4 + 3) * 72 + key] = __float2half_rn(vv.w);
            }
        }
        __syncthreads();

        // S = Q K^T (rows wid*16..+16, 64 keys).
        float s[8][4];
#pragma unroll
        for (int nt = 0; nt < 8; ++nt)
#pragma unroll
            for (int r = 0; r < 4; ++r) s[nt][r] = 0.f;

#pragma unroll
        for (int ks = 0; ks < 4; ++ks) {
            const int kc = ks * 8 + (lane & 3);
#pragma unroll
            for (int nt = 0; nt < 8; ++nt) {
                const int key = nt * 8 + (lane >> 2);
                uint32_t bf[2];
                bf[0] = Ks[key * 36 + kc];
                bf[1] = Ks[key * 36 + kc + 4];
                mma_f16(s[nt], aq[ks], bf);
            }
        }

        // Online softmax (quad reduction: lanes xor 1,2 share the row).
#pragma unroll
        for (int r = 0; r < 2; ++r) {
            float tm = -INFINITY;
#pragma unroll
            for (int nt = 0; nt < 8; ++nt)
                tm = fmaxf(tm, fmaxf(s[nt][2 * r], s[nt][2 * r + 1]));
            tm = fmaxf(tm, __shfl_xor_sync(0xffffffffu, tm, 1));
            tm = fmaxf(tm, __shfl_xor_sync(0xffffffffu, tm, 2));

            float mn = fmaxf(m_i[r], tm);
            float alpha = __expf(m_i[r] - mn);
            m_i[r] = mn;

            float ps = 0.f;
#pragma unroll
            for (int nt = 0; nt < 8; ++nt) {
                s[nt][2 * r]     = __expf(s[nt][2 * r] - mn);
                s[nt][2 * r + 1] = __expf(s[nt][2 * r + 1] - mn);
                ps += s[nt][2 * r] + s[nt][2 * r + 1];
            }
            ps += __shfl_xor_sync(0xffffffffu, ps, 1);
            ps += __shfl_xor_sync(0xffffffffu, ps, 2);

            l_i[r] = l_i[r] * alpha + ps;
#pragma unroll
            for (int nt = 0; nt < 8; ++nt) {
                o[nt][2 * r]     *= alpha;
                o[nt][2 * r + 1] *= alpha;
            }
        }

        // O += P V. C-frag of S == A-frag of PV: pack in registers, no smem.
#pragma unroll
        for (int ks = 0; ks < 4; ++ks) {
            uint32_t ap[4];
            ap[0] = pack2h(s[2 * ks][0],     s[2 * ks][1]);
            ap[1] = pack2h(s[2 * ks][2],     s[2 * ks][3]);
            ap[2] = pack2h(s[2 * ks + 1][0], s[2 * ks + 1][1]);
            ap[3] = pack2h(s[2 * ks + 1][2], s[2 * ks + 1][3]);
            const int kc = ks * 8 + (lane & 3);
#pragma unroll
            for (int nt = 0; nt < 8; ++nt) {
                const int dd = nt * 8 + (lane >> 2);
                uint32_t bf[2];
                bf[0] = Vt[dd * 36 + kc];
                bf[1] = Vt[dd * 36 + kc + 4];
                mma_f16(o[nt], ap, bf);
            }
        }
        __syncthreads();                // before next tile restages K/V
    }

    // Epilogue: normalize & store ctx.
#pragma unroll
    for (int r = 0; r < 2; ++r) {
        const float inv = 1.0f / l_i[r];
        const int row = s0 + wid * 16 + (lane >> 2) + r * 8;
#pragma unroll
        for (int nt = 0; nt < 8; ++nt) {
            const int dd = nt * 8 + (lane & 3) * 2;
            float2 v = make_float2(o[nt][2 * r] * inv, o[nt][2 * r + 1] * inv);
            *(float2*)&g_ctx[base + (size_t)row * Csz + dd] = v;
        }
    }
}

// ---------------------------------------------------------------------------
// Launch
// ---------------------------------------------------------------------------
extern "C" void kernel_launch(void* const* d_in, const int* in_sizes, int n_in,
                              void* d_out, int out_size) {
    const float* x    = (const float*)d_in[0];
    const float* skip = (const float*)d_in[1];
    const float* Wq   = (const float*)d_in[2];
    const float* bq   = (const float*)d_in[3];
    const float* Wk   = (const float*)d_in[4];
    const float* bk   = (const float*)d_in[5];
    const float* Wv   = (const float*)d_in[6];
    const float* bv   = (const float*)d_in[7];
    const float* Wo   = (const float*)d_in[8];
    const float* bo   = (const float*)d_in[9];
    float* out = (float*)d_out;

    void* p_ctx = nullptr;
    cudaGetSymbolAddress(&p_ctx, g_ctx);

    dim3 qkvgrid(Csz / 128, Mtot / 128, 3);   // (4, 64, 3)
    qkv_gemm<<<qkvgrid, 256>>>(x, Wq, bq, Wk, bk, Wv, bv);

    dim3 agrid(Ssz / 128, Hsz, Bsz);          // (8, 8, 8)
    attn_tc<<<agrid, 256>>>();

    dim3 ogrid(Csz / 128, Mtot / 128);        // (4, 64)
    o_gemm<<<ogrid, 256>>>((const float*)p_ctx, Wo, bo, skip, out);
}

// round 11
// speedup vs baseline: 6.6132x; 1.3119x over previous
#include <cuda_runtime.h>
#include <cuda_fp16.h>
#include <cstdint>
#include <math.h>

#define Bsz 8
#define Ssz 1024
#define Csz 512
#define Hsz 8
#define DHsz 64
#define Mtot (Bsz * Ssz)   // 8192
#define WN (Csz * Csz)

// ---------------------------------------------------------------------------
// Scratch (__device__ globals; no allocation allowed)
// ---------------------------------------------------------------------------
__device__ __half g_xh[Mtot * Csz];     // x in fp16
__device__ __half g_wh[4 * WN];         // Wq,Wk,Wv,Wo in fp16
__device__ __half g_qh[Mtot * Csz];     // Q, pre-scaled by 1/8, [b,s,c]
__device__ __half g_kh[Mtot * Csz];     // K, [b,s,c]
__device__ __half g_vt[Mtot * Csz];     // V transposed, [b,h,d,s]
__device__ __half g_ctxh[Mtot * Csz];   // attention output, fp16 [b,s,c]

// ---------------------------------------------------------------------------
// Helpers (all sm_80+ core PTX — nothing arch-'a' gated)
// ---------------------------------------------------------------------------
__device__ __forceinline__ uint32_t pack2h(float a, float b) {
    __half2 h = __floats2half2_rn(a, b);
    return *(uint32_t*)&h;
}
__device__ __forceinline__ uint32_t su32(const void* p) {
    return (uint32_t)__cvta_generic_to_shared(p);
}
__device__ __forceinline__ void cp16(uint32_t dst, const void* src) {
    asm volatile("cp.async.ca.shared.global [%0], [%1], 16;\n" ::"r"(dst),
                 "l"(src));
}
#define CP_COMMIT() asm volatile("cp.async.commit_group;\n" ::: "memory")
#define CP_WAIT1()  asm volatile("cp.async.wait_group 1;\n" ::: "memory")
#define CP_WAIT0()  asm volatile("cp.async.wait_group 0;\n" ::: "memory")

// D += A*B, m16n8k16 f16 in / f32 accum.
__device__ __forceinline__ void mma_f16(float* c, const uint32_t* a,
                                        const uint32_t* b) {
    asm volatile(
        "mma.sync.aligned.m16n8k16.row.col.f32.f16.f16.f32 "
        "{%0,%1,%2,%3}, {%4,%5,%6,%7}, {%8,%9}, {%0,%1,%2,%3};"
        : "+f"(c[0]), "+f"(c[1]), "+f"(c[2]), "+f"(c[3])
        : "r"(a[0]), "r"(a[1]), "r"(a[2]), "r"(a[3]), "r"(b[0]), "r"(b[1]));
}

// ---------------------------------------------------------------------------
// fp32 -> fp16 conversion
// ---------------------------------------------------------------------------
__global__ void cvt_f2h(const float* __restrict__ in, __half* __restrict__ out,
                        int n) {
    int i = (blockIdx.x * blockDim.x + threadIdx.x) * 4;
    if (i < n) {
        float4 v = *(const float4*)&in[i];
        uint32_t* o = (uint32_t*)&out[i];
        o[0] = pack2h(v.x, v.y);
        o[1] = pack2h(v.z, v.w);
    }
}

// ---------------------------------------------------------------------------
// fp16 GEMM core, cp.async double-buffered.
// out[m][n] = sum_c A[m][c] * Bw[n][c] (+bias etc. per MODE epilogue)
// BM=BN=128, BK=64 halves (32 u32, 8 x 16B chunks per row).
// 256 thr / 8 warps, warp tile 64x32.
// smem: 2 bufs x (A[128][36] + B[128][36]) u32 = 73,728 B dynamic.
// MODE: 0=Q(half,scaled) 1=K(half) 2=V(half,transposed) 3=O(f32,+bias+skip)
// ---------------------------------------------------------------------------
template <int MODE>
__device__ __forceinline__
void gemm_core(const __half* __restrict__ A, const __half* __restrict__ Bw,
               const float* __restrict__ bias, const float* __restrict__ skip,
               float* __restrict__ outf, int m0, int n0) {
    extern __shared__ uint32_t sm[];
    const int tid = threadIdx.x, lane = tid & 31, wid = tid >> 5;
    const int wm = (wid >> 2) * 64, wn = (wid & 3) * 32;

    float acc[4][4][4];
#pragma unroll
    for (int mt = 0; mt < 4; ++mt)
#pragma unroll
        for (int nt = 0; nt < 4; ++nt)
#pragma unroll
            for (int r = 0; r < 4; ++r) acc[mt][nt][r] = 0.f;

    // stage k-block kb into buffer buf: 128 rows x 8 chunks per array
    auto stage = [&](int kb, int buf) {
        uint32_t* As = sm + buf * 9216;
        uint32_t* Bs = As + 4608;
        const int k0 = kb * 64;
#pragma unroll
        for (int i = 0; i < 4; ++i) {
            int e = tid + i * 256;            // 0..1023
            int r = e >> 3, ch = e & 7;
            cp16(su32(&As[r * 36 + ch * 4]),
                 A + (size_t)(m0 + r) * Csz + k0 + ch * 8);
            cp16(su32(&Bs[r * 36 + ch * 4]),
                 Bw + (size_t)(n0 + r) * Csz + k0 + ch * 8);
        }
    };

    stage(0, 0);
    CP_COMMIT();

    for (int kb = 0; kb < 8; ++kb) {
        if (kb < 7) {
            stage(kb + 1, (kb + 1) & 1);
            CP_COMMIT();
            CP_WAIT1();
        } else {
            CP_WAIT0();
        }
        __syncthreads();

        const uint32_t* As = sm + (kb & 1) * 9216;
        const uint32_t* Bs = As + 4608;
#pragma unroll
        for (int ks = 0; ks < 4; ++ks) {
            const int kc = ks * 8 + (lane & 3);
            uint32_t af[4][4], bf[4][2];
            const int ar = wm + (lane >> 2);
#pragma unroll
            for (int mt = 0; mt < 4; ++mt) {
                af[mt][0] = As[(ar + mt * 16) * 36 + kc];
                af[mt][1] = As[(ar + mt * 16 + 8) * 36 + kc];
                af[mt][2] = As[(ar + mt * 16) * 36 + kc + 4];
                af[mt][3] = As[(ar + mt * 16 + 8) * 36 + kc + 4];
            }
            const int br = wn + (lane >> 2);
#pragma unroll
            for (int nt = 0; nt < 4; ++nt) {
                bf[nt][0] = Bs[(br + nt * 8) * 36 + kc];
                bf[nt][1] = Bs[(br + nt * 8) * 36 + kc + 4];
            }
#pragma unroll
            for (int mt = 0; mt < 4; ++mt)
#pragma unroll
                for (int nt = 0; nt < 4; ++nt)
                    mma_f16(acc[mt][nt], af[mt], bf[nt]);
        }
        __syncthreads();
    }

    // Epilogue
#pragma unroll
    for (int mt = 0; mt < 4; ++mt) {
        const int r0 = m0 + wm + mt * 16 + (lane >> 2);
#pragma unroll
        for (int nt = 0; nt < 4; ++nt) {
            const int c = n0 + wn + nt * 8 + (lane & 3) * 2;
            float b0 = bias[c], b1 = bias[c + 1];
            float v00 = acc[mt][nt][0] + b0, v01 = acc[mt][nt][1] + b1;
            float v10 = acc[mt][nt][2] + b0, v11 = acc[mt][nt][3] + b1;
            if (MODE == 0) {
                *(uint32_t*)&g_qh[(size_t)r0 * Csz + c] =
                    pack2h(v00 * 0.125f, v01 * 0.125f);
                *(uint32_t*)&g_qh[(size_t)(r0 + 8) * Csz + c] =
                    pack2h(v10 * 0.125f, v11 * 0.125f);
            } else if (MODE == 1) {
                *(uint32_t*)&g_kh[(size_t)r0 * Csz + c] = pack2h(v00, v01);
                *(uint32_t*)&g_kh[(size_t)(r0 + 8) * Csz + c] = pack2h(v10, v11);
            } else if (MODE == 2) {
                // transposed: g_vt[(b*H+h)*64+dh][s]
                const int h = c >> 6, dh = c & 63;
                const int bb = r0 >> 10, s = r0 & 1023;
                const size_t rowd = (size_t)(bb * Hsz + h) * DHsz;
                g_vt[(rowd + dh) * Ssz + s]         = __float2half_rn(v00);
                g_vt[(rowd + dh + 1) * Ssz + s]     = __float2half_rn(v01);
                g_vt[(rowd + dh) * Ssz + s + 8]     = __float2half_rn(v10);
                g_vt[(rowd + dh + 1) * Ssz + s + 8] = __float2half_rn(v11);
            } else {
                const float* s0p = &skip[(size_t)r0 * Csz + c];
                const float* s1p = &skip[(size_t)(r0 + 8) * Csz + c];
                float2 w0 = make_float2(v00 + s0p[0], v01 + s0p[1]);
                float2 w1 = make_float2(v10 + s1p[0], v11 + s1p[1]);
                *(float2*)&outf[(size_t)r0 * Csz + c] = w0;
                *(float2*)&outf[(size_t)(r0 + 8) * Csz + c] = w1;
            }
        }
    }
}

#define GEMM_SMEM (2 * 2 * 128 * 36 * 4)   // 73,728 B

__global__ __launch_bounds__(256)
void qkv_gemm(const float* __restrict__ bq, const float* __restrict__ bk,
              const float* __restrict__ bv) {
    const int m0 = blockIdx.y * 128, n0 = blockIdx.x * 128;
    if (blockIdx.z == 0)
        gemm_core<0>(g_xh, g_wh, bq, nullptr, nullptr, m0, n0);
    else if (blockIdx.z == 1)
        gemm_core<1>(g_xh, g_wh + WN, bk, nullptr, nullptr, m0, n0);
    else
        gemm_core<2>(g_xh, g_wh + 2 * WN, bv, nullptr, nullptr, m0, n0);
}

__global__ __launch_bounds__(256)
void o_gemm(const float* __restrict__ bo, const float* __restrict__ skip,
            float* __restrict__ out) {
    gemm_core<3>(g_ctxh, g_wh + 3 * WN, bo, skip, out,
                 blockIdx.y * 128, blockIdx.x * 128);
}

// ---------------------------------------------------------------------------
// Flash attention: fp16 mma, register-direct P, cp.async double-buffered K/V.
// 256 thr / 8 warps; q-tile 128, key-tile 64, DH=64.
// smem: Qs[128][36] + 2 x (Ks[64][36] + Vt[64][36]) u32 = 55,296 B dynamic.
// ---------------------------------------------------------------------------
#define ATTN_SMEM ((128 * 36 + 2 * 2 * 64 * 36) * 4)

__global__ __launch_bounds__(256)
void attn_tc() {
    extern __shared__ uint32_t sm[];
    uint32_t* Qs = sm;   // [128][36]

    const int qt = blockIdx.x, h = blockIdx.y, b = blockIdx.z;
    const int s0 = qt * 128;
    const int tid = threadIdx.x, lane = tid & 31, wid = tid >> 5;
    const size_t baseq = ((size_t)b * Ssz) * Csz + h * DHsz;     // g_qh/g_kh/g_ctxh
    const size_t basev = ((size_t)(b * Hsz + h) * DHsz) * Ssz;   // g_vt

    // 64 rows x 8 chunks per array; 256 threads -> 2 chunks each per array.
    auto stageKV = [&](int kt, int buf) {
        const int k0 = kt * 64;
        uint32_t* Ks = sm + 4608 + buf * 4608;
        uint32_t* Vs = Ks + 2304;
#pragma unroll
        for (int i = 0; i < 2; ++i) {
            int e = tid + i * 256;       // 0..511
            int r = e >> 3, ch = e & 7;
            cp16(su32(&Ks[r * 36 + ch * 4]),
                 g_kh + baseq + (size_t)(k0 + r) * Csz + ch * 8);
            cp16(su32(&Vs[r * 36 + ch * 4]),
                 g_vt + basev + (size_t)r * Ssz + k0 + ch * 8);
        }
    };

    // Stage Q (+KV0 in the same group), then KV1.
#pragma unroll
    for (int i = 0; i < 4; ++i) {
        int e = tid + i * 256;           // 0..1023 (128 rows x 8 chunks)
        int r = e >> 3, ch = e & 7;
        cp16(su32(&Qs[r * 36 + ch * 4]),
             g_qh + baseq + (size_t)(s0 + r) * Csz + ch * 8);
    }
    stageKV(0, 0);
    CP_COMMIT();
    stageKV(1, 1);
    CP_COMMIT();
    CP_WAIT1();          // Q + KV0 ready
    __syncthreads();

    // Extract Q fragments (Q already pre-scaled in fp16).
    uint32_t aq[4][4];
    {
        const int ar = wid * 16 + (lane >> 2);
#pragma unroll
        for (int ks = 0; ks < 4; ++ks) {
            const int kc = ks * 8 + (lane & 3);
            aq[ks][0] = Qs[ar * 36 + kc];
            aq[ks][1] = Qs[(ar + 8) * 36 + kc];
            aq[ks][2] = Qs[ar * 36 + kc + 4];
            aq[ks][3] = Qs[(ar + 8) * 36 + kc + 4];
        }
    }

    float m_i[2] = {-INFINITY, -INFINITY};
    float l_i[2] = {0.f, 0.f};
    float o[8][4];
#pragma unroll
    for (int nt = 0; nt < 8; ++nt)
#pragma unroll
        for (int r = 0; r < 4; ++r) o[nt][r] = 0.f;

    for (int kt = 0; kt < 16; ++kt) {
        const uint32_t* Ks = sm + 4608 + (kt & 1) * 4608;
        const uint32_t* Vt = Ks + 2304;

        // S = Q K^T  (warp rows wid*16..+16, 64 keys)
        float s[8][4];
#pragma unroll
        for (int nt = 0; nt < 8; ++nt)
#pragma unroll
            for (int r = 0; r < 4; ++r) s[nt][r] = 0.f;

#pragma unroll
        for (int ks = 0; ks < 4; ++ks) {
            const int kc = ks * 8 + (lane & 3);
#pragma unroll
            for (int nt = 0; nt < 8; ++nt) {
                const int key = nt * 8 + (lane >> 2);
                uint32_t bf[2];
                bf[0] = Ks[key * 36 + kc];
                bf[1] = Ks[key * 36 + kc + 4];
                mma_f16(s[nt], aq[ks], bf);
            }
        }

        // Online softmax (lane quad xor 1,2 shares the row).
#pragma unroll
        for (int r = 0; r < 2; ++r) {
            float tm = -INFINITY;
#pragma unroll
            for (int nt = 0; nt < 8; ++nt)
                tm = fmaxf(tm, fmaxf(s[nt][2 * r], s[nt][2 * r + 1]));
            tm = fmaxf(tm, __shfl_xor_sync(0xffffffffu, tm, 1));
            tm = fmaxf(tm, __shfl_xor_sync(0xffffffffu, tm, 2));

            float mn = fmaxf(m_i[r], tm);
            float alpha = __expf(m_i[r] - mn);
            m_i[r] = mn;

            float ps = 0.f;
#pragma unroll
            for (int nt = 0; nt < 8; ++nt) {
                s[nt][2 * r]     = __expf(s[nt][2 * r] - mn);
                s[nt][2 * r + 1] = __expf(s[nt][2 * r + 1] - mn);
                ps += s[nt][2 * r] + s[nt][2 * r + 1];
            }
            ps += __shfl_xor_sync(0xffffffffu, ps, 1);
            ps += __shfl_xor_sync(0xffffffffu, ps, 2);

            l_i[r] = l_i[r] * alpha + ps;
#pragma unroll
            for (int nt = 0; nt < 8; ++nt) {
                o[nt][2 * r]     *= alpha;
                o[nt][2 * r + 1] *= alpha;
            }
        }

        // O += P V  (P packed straight from registers)
#pragma unroll
        for (int ks = 0; ks < 4; ++ks) {
            uint32_t ap[4];
            ap[0] = pack2h(s[2 * ks][0],     s[2 * ks][1]);
            ap[1] = pack2h(s[2 * ks][2],     s[2 * ks][3]);
            ap[2] = pack2h(s[2 * ks + 1][0], s[2 * ks + 1][1]);
            ap[3] = pack2h(s[2 * ks + 1][2], s[2 * ks + 1][3]);
            const int kc = ks * 8 + (lane & 3);
#pragma unroll
            for (int nt = 0; nt < 8; ++nt) {
                const int dd = nt * 8 + (lane >> 2);
                uint32_t bf[2];
                bf[0] = Vt[dd * 36 + kc];
                bf[1] = Vt[dd * 36 + kc + 4];
                mma_f16(o[nt], ap, bf);
            }
        }

        __syncthreads();                       // done reading buf[kt&1]
        if (kt + 2 < 16) {
            stageKV(kt + 2, kt & 1);
            CP_COMMIT();
        }
        if (kt < 15) {
            if (kt + 2 < 16) CP_WAIT1();
            else             CP_WAIT0();
            __syncthreads();                   // buf[(kt+1)&1] ready
        }
    }

    // Epilogue: normalize, write ctx as fp16 (consumed by o_gemm).
#pragma unroll
    for (int r = 0; r < 2; ++r) {
        const float inv = 1.0f / l_i[r];
        const int row = s0 + wid * 16 + (lane >> 2) + r * 8;
#pragma unroll
        for (int nt = 0; nt < 8; ++nt) {
            const int dd = nt * 8 + (lane & 3) * 2;
            *(uint32_t*)&g_ctxh[baseq + (size_t)row * Csz + dd] =
                pack2h(o[nt][2 * r] * inv, o[nt][2 * r + 1] * inv);
        }
    }
}

// ---------------------------------------------------------------------------
// Launch
// ---------------------------------------------------------------------------
extern "C" void kernel_launch(void* const* d_in, const int* in_sizes, int n_in,
                              void* d_out, int out_size) {
    const float* x    = (const float*)d_in[0];
    const float* skip = (const float*)d_in[1];
    const float* Wq   = (const float*)d_in[2];
    const float* bq   = (const float*)d_in[3];
    const float* Wk   = (const float*)d_in[4];
    const float* bk   = (const float*)d_in[5];
    const float* Wv   = (const float*)d_in[6];
    const float* bv   = (const float*)d_in[7];
    const float* Wo   = (const float*)d_in[8];
    const float* bo   = (const float*)d_in[9];
    float* out = (float*)d_out;

    void *p_xh, *p_wh;
    cudaGetSymbolAddress(&p_xh, g_xh);
    cudaGetSymbolAddress(&p_wh, g_wh);
    __half* xh = (__half*)p_xh;
    __half* wh = (__half*)p_wh;

    // fp32 -> fp16 conversions
    cvt_f2h<<<(Mtot * Csz / 4 + 255) / 256, 256>>>(x, xh, Mtot * Csz);
    cvt_f2h<<<(WN / 4 + 255) / 256, 256>>>(Wq, wh + 0 * WN, WN);
    cvt_f2h<<<(WN / 4 + 255) / 256, 256>>>(Wk, wh + 1 * WN, WN);
    cvt_f2h<<<(WN / 4 + 255) / 256, 256>>>(Wv, wh + 2 * WN, WN);
    cvt_f2h<<<(WN / 4 + 255) / 256, 256>>>(Wo, wh + 3 * WN, WN);

    cudaFuncSetAttribute(qkv_gemm, cudaFuncAttributeMaxDynamicSharedMemorySize,
                         GEMM_SMEM);
    cudaFuncSetAttribute(o_gemm, cudaFuncAttributeMaxDynamicSharedMemorySize,
                         GEMM_SMEM);
    cudaFuncSetAttribute(attn_tc, cudaFuncAttributeMaxDynamicSharedMemorySize,
                         ATTN_SMEM);

    dim3 qkvgrid(Csz / 128, Mtot / 128, 3);   // (4, 64, 3)
    qkv_gemm<<<qkvgrid, 256, GEMM_SMEM>>>(bq, bk, bv);

    dim3 agrid(Ssz / 128, Hsz, Bsz);          // (8, 8, 8)
    attn_tc<<<agrid, 256, ATTN_SMEM>>>();

    dim3 ogrid(Csz / 128, Mtot / 128);        // (4, 64)
    o_gemm<<<ogrid, 256, GEMM_SMEM>>>(bo, skip, out);
}

// round 15
// speedup vs baseline: 7.0214x; 1.0617x over previous
#include <cuda_runtime.h>
#include <cuda_fp16.h>
#include <cstdint>
#include <math.h>

#define Bsz 8
#define Ssz 1024
#define Csz 512
#define Hsz 8
#define DHsz 64
#define Mtot (Bsz * Ssz)   // 8192
#define WN (Csz * Csz)
#define LOG2E 1.44269504088896340736f

// ---------------------------------------------------------------------------
// Scratch (__device__ globals; no allocation allowed)
// ---------------------------------------------------------------------------
__device__ __half g_xh[Mtot * Csz];     // x in fp16
__device__ __half g_wh[4 * WN];         // Wq,Wk,Wv,Wo in fp16
__device__ __half g_qh[Mtot * Csz];     // Q, pre-scaled by log2e/8, [b,s,c]
__device__ __half g_kh[Mtot * Csz];     // K, [b,s,c]
__device__ __half g_vt[Mtot * Csz];     // V transposed, [b,h,d,s]
__device__ __half g_ctxh[Mtot * Csz];   // attention output, fp16 [b,s,c]

// ---------------------------------------------------------------------------
// Helpers (all sm_80+ core PTX — nothing arch-'a' gated)
// ---------------------------------------------------------------------------
__device__ __forceinline__ uint32_t pack2h(float a, float b) {
    __half2 h = __floats2half2_rn(a, b);
    return *(uint32_t*)&h;
}
__device__ __forceinline__ uint32_t su32(const void* p) {
    return (uint32_t)__cvta_generic_to_shared(p);
}
__device__ __forceinline__ void cp16(uint32_t dst, const void* src) {
    asm volatile("cp.async.ca.shared.global [%0], [%1], 16;\n" ::"r"(dst),
                 "l"(src));
}
#define CP_COMMIT() asm volatile("cp.async.commit_group;\n" ::: "memory")
#define CP_WAIT1()  asm volatile("cp.async.wait_group 1;\n" ::: "memory")
#define CP_WAIT0()  asm volatile("cp.async.wait_group 0;\n" ::: "memory")

__device__ __forceinline__ float ex2(float x) {
    float r;
    asm("ex2.approx.f32 %0, %1;" : "=f"(r) : "f"(x));
    return r;
}

// D += A*B, m16n8k16 f16 in / f32 accum.
__device__ __forceinline__ void mma_f16(float* c, const uint32_t* a,
                                        const uint32_t* b) {
    asm volatile(
        "mma.sync.aligned.m16n8k16.row.col.f32.f16.f16.f32 "
        "{%0,%1,%2,%3}, {%4,%5,%6,%7}, {%8,%9}, {%0,%1,%2,%3};"
        : "+f"(c[0]), "+f"(c[1]), "+f"(c[2]), "+f"(c[3])
        : "r"(a[0]), "r"(a[1]), "r"(a[2]), "r"(a[3]), "r"(b[0]), "r"(b[1]));
}

// ---------------------------------------------------------------------------
// Single fused fp32 -> fp16 conversion: x then Wq,Wk,Wv,Wo.
// Index space in float4 units: [0, NX4) = x, then 4 weight regions of NW4.
// ---------------------------------------------------------------------------
#define NX4 (Mtot * Csz / 4)   // 1,048,576
#define NW4 (WN / 4)           // 65,536
#define NCVT4 (NX4 + 4 * NW4)  // 1,310,720

__global__ void cvt_all(const float* __restrict__ x,
                        const float* __restrict__ Wq,
                        const float* __restrict__ Wk,
                        const float* __restrict__ Wv,
                        const float* __restrict__ Wo) {
    int q = blockIdx.x * blockDim.x + threadIdx.x;
    if (q >= NCVT4) return;
    const float* src;
    __half* dst;
    int idx;
    if (q < NX4) {
        src = x; dst = g_xh; idx = q;
    } else {
        int w = (q - NX4) / NW4;          // 0..3
        idx = (q - NX4) - w * NW4;
        src = (w == 0) ? Wq : (w == 1) ? Wk : (w == 2) ? Wv : Wo;
        dst = g_wh + w * WN;
    }
    float4 v = *(const float4*)&src[idx * 4];
    uint32_t* o = (uint32_t*)&dst[idx * 4];
    o[0] = pack2h(v.x, v.y);
    o[1] = pack2h(v.z, v.w);
}

// ---------------------------------------------------------------------------
// fp16 GEMM core, cp.async double-buffered.
// out[m][n] = sum_c A[m][c] * Bw[n][c] (+bias etc. per MODE epilogue)
// BM=BN=128, BK=64 halves (32 u32, 8 x 16B chunks per row).
// 256 thr / 8 warps, warp tile 64x32.
// smem: 2 bufs x (A[128][36] + B[128][36]) u32 = 73,728 B dynamic.
// MODE: 0=Q(half,scaled by log2e/8) 1=K(half) 2=V(half,transposed) 3=O(f32)
// ---------------------------------------------------------------------------
template <int MODE>
__device__ __forceinline__
void gemm_core(const __half* __restrict__ A, const __half* __restrict__ Bw,
               const float* __restrict__ bias, const float* __restrict__ skip,
               float* __restrict__ outf, int m0, int n0) {
    extern __shared__ uint32_t sm[];
    const int tid = threadIdx.x, lane = tid & 31, wid = tid >> 5;
    const int wm = (wid >> 2) * 64, wn = (wid & 3) * 32;

    float acc[4][4][4];
#pragma unroll
    for (int mt = 0; mt < 4; ++mt)
#pragma unroll
        for (int nt = 0; nt < 4; ++nt)
#pragma unroll
            for (int r = 0; r < 4; ++r) acc[mt][nt][r] = 0.f;

    auto stage = [&](int kb, int buf) {
        uint32_t* As = sm + buf * 9216;
        uint32_t* Bs = As + 4608;
        const int k0 = kb * 64;
#pragma unroll
        for (int i = 0; i < 4; ++i) {
            int e = tid + i * 256;            // 0..1023
            int r = e >> 3, ch = e & 7;
            cp16(su32(&As[r * 36 + ch * 4]),
                 A + (size_t)(m0 + r) * Csz + k0 + ch * 8);
            cp16(su32(&Bs[r * 36 + ch * 4]),
                 Bw + (size_t)(n0 + r) * Csz + k0 + ch * 8);
        }
    };

    stage(0, 0);
    CP_COMMIT();

    for (int kb = 0; kb < 8; ++kb) {
        if (kb < 7) {
            stage(kb + 1, (kb + 1) & 1);
            CP_COMMIT();
            CP_WAIT1();
        } else {
            CP_WAIT0();
        }
        __syncthreads();

        const uint32_t* As = sm + (kb & 1) * 9216;
        const uint32_t* Bs = As + 4608;
#pragma unroll
        for (int ks = 0; ks < 4; ++ks) {
            const int kc = ks * 8 + (lane & 3);
            uint32_t af[4][4], bf[4][2];
            const int ar = wm + (lane >> 2);
#pragma unroll
            for (int mt = 0; mt < 4; ++mt) {
                af[mt][0] = As[(ar + mt * 16) * 36 + kc];
                af[mt][1] = As[(ar + mt * 16 + 8) * 36 + kc];
                af[mt][2] = As[(ar + mt * 16) * 36 + kc + 4];
                af[mt][3] = As[(ar + mt * 16 + 8) * 36 + kc + 4];
            }
            const int br = wn + (lane >> 2);
#pragma unroll
            for (int nt = 0; nt < 4; ++nt) {
                bf[nt][0] = Bs[(br + nt * 8) * 36 + kc];
                bf[nt][1] = Bs[(br + nt * 8) * 36 + kc + 4];
            }
#pragma unroll
            for (int mt = 0; mt < 4; ++mt)
#pragma unroll
                for (int nt = 0; nt < 4; ++nt)
                    mma_f16(acc[mt][nt], af[mt], bf[nt]);
        }
        __syncthreads();
    }

    // Epilogue
#pragma unroll
    for (int mt = 0; mt < 4; ++mt) {
        const int r0 = m0 + wm + mt * 16 + (lane >> 2);
#pragma unroll
        for (int nt = 0; nt < 4; ++nt) {
            const int c = n0 + wn + nt * 8 + (lane & 3) * 2;
            float b0 = bias[c], b1 = bias[c + 1];
            float v00 = acc[mt][nt][0] + b0, v01 = acc[mt][nt][1] + b1;
            float v10 = acc[mt][nt][2] + b0, v11 = acc[mt][nt][3] + b1;
            if (MODE == 0) {
                const float qs = 0.125f * LOG2E;
                *(uint32_t*)&g_qh[(size_t)r0 * Csz + c] =
                    pack2h(v00 * qs, v01 * qs);
                *(uint32_t*)&g_qh[(size_t)(r0 + 8) * Csz + c] =
                    pack2h(v10 * qs, v11 * qs);
            } else if (MODE == 1) {
                *(uint32_t*)&g_kh[(size_t)r0 * Csz + c] = pack2h(v00, v01);
                *(uint32_t*)&g_kh[(size_t)(r0 + 8) * Csz + c] = pack2h(v10, v11);
            } else if (MODE == 2) {
                // transposed: g_vt[(b*H+h)*64+dh][s]
                const int h = c >> 6, dh = c & 63;
                const int bb = r0 >> 10, s = r0 & 1023;
                const size_t rowd = (size_t)(bb * Hsz + h) * DHsz;
                g_vt[(rowd + dh) * Ssz + s]         = __float2half_rn(v00);
                g_vt[(rowd + dh + 1) * Ssz + s]     = __float2half_rn(v01);
                g_vt[(rowd + dh) * Ssz + s + 8]     = __float2half_rn(v10);
                g_vt[(rowd + dh + 1) * Ssz + s + 8] = __float2half_rn(v11);
            } else {
                const float* s0p = &skip[(size_t)r0 * Csz + c];
                const float* s1p = &skip[(size_t)(r0 + 8) * Csz + c];
                float2 w0 = make_float2(v00 + s0p[0], v01 + s0p[1]);
                float2 w1 = make_float2(v10 + s1p[0], v11 + s1p[1]);
                *(float2*)&outf[(size_t)r0 * Csz + c] = w0;
                *(float2*)&outf[(size_t)(r0 + 8) * Csz + c] = w1;
            }
        }
    }
}

#define GEMM_SMEM (2 * 2 * 128 * 36 * 4)   // 73,728 B

__global__ __launch_bounds__(256)
void qkv_gemm(const float* __restrict__ bq, const float* __restrict__ bk,
              const float* __restrict__ bv) {
    const int m0 = blockIdx.y * 128, n0 = blockIdx.x * 128;
    if (blockIdx.z == 0)
        gemm_core<0>(g_xh, g_wh, bq, nullptr, nullptr, m0, n0);
    else if (blockIdx.z == 1)
        gemm_core<1>(g_xh, g_wh + WN, bk, nullptr, nullptr, m0, n0);
    else
        gemm_core<2>(g_xh, g_wh + 2 * WN, bv, nullptr, nullptr, m0, n0);
}

__global__ __launch_bounds__(256)
void o_gemm(const float* __restrict__ bo, const float* __restrict__ skip,
            float* __restrict__ out) {
    gemm_core<3>(g_ctxh, g_wh + 3 * WN, bo, skip, out,
                 blockIdx.y * 128, blockIdx.x * 128);
}

// ---------------------------------------------------------------------------
// Flash attention: fp16 mma, register-direct P, cp.async double-buffered K/V.
// Base-2 softmax: Q pre-scaled by log2e/8, exp2 for P and alpha.
// 256 thr / 8 warps; q-tile 128, key-tile 64, DH=64.
// smem: Qs[128][36] + 2 x (Ks[64][36] + Vt[64][36]) u32 = 55,296 B dynamic.
// ---------------------------------------------------------------------------
#define ATTN_SMEM ((128 * 36 + 2 * 2 * 64 * 36) * 4)

__global__ __launch_bounds__(256)
void attn_tc() {
    extern __shared__ uint32_t sm[];
    uint32_t* Qs = sm;   // [128][36]

    const int qt = blockIdx.x, h = blockIdx.y, b = blockIdx.z;
    const int s0 = qt * 128;
    const int tid = threadIdx.x, lane = tid & 31, wid = tid >> 5;
    const size_t baseq = ((size_t)b * Ssz) * Csz + h * DHsz;     // g_qh/g_kh/g_ctxh
    const size_t basev = ((size_t)(b * Hsz + h) * DHsz) * Ssz;   // g_vt

    auto stageKV = [&](int kt, int buf) {
        const int k0 = kt * 64;
        uint32_t* Ks = sm + 4608 + buf * 4608;
        uint32_t* Vs = Ks + 2304;
#pragma unroll
        for (int i = 0; i < 2; ++i) {
            int e = tid + i * 256;       // 0..511
            int r = e >> 3, ch = e & 7;
            cp16(su32(&Ks[r * 36 + ch * 4]),
                 g_kh + baseq + (size_t)(k0 + r) * Csz + ch * 8);
            cp16(su32(&Vs[r * 36 + ch * 4]),
                 g_vt + basev + (size_t)r * Ssz + k0 + ch * 8);
        }
    };

    // Stage Q (+KV0 in the same group), then KV1.
#pragma unroll
    for (int i = 0; i < 4; ++i) {
        int e = tid + i * 256;           // 0..1023 (128 rows x 8 chunks)
        int r = e >> 3, ch = e & 7;
        cp16(su32(&Qs[r * 36 + ch * 4]),
             g_qh + baseq + (size_t)(s0 + r) * Csz + ch * 8);
    }
    stageKV(0, 0);
    CP_COMMIT();
    stageKV(1, 1);
    CP_COMMIT();
    CP_WAIT1();          // Q + KV0 ready
    __syncthreads();

    // Extract Q fragments (Q already pre-scaled in fp16).
    uint32_t aq[4][4];
    {
        const int ar = wid * 16 + (lane >> 2);
#pragma unroll
        for (int ks = 0; ks < 4; ++ks) {
            const int kc = ks * 8 + (lane & 3);
            aq[ks][0] = Qs[ar * 36 + kc];
            aq[ks][1] = Qs[(ar + 8) * 36 + kc];
            aq[ks][2] = Qs[ar * 36 + kc + 4];
            aq[ks][3] = Qs[(ar + 8) * 36 + kc + 4];
        }
    }

    float m_i[2] = {-INFINITY, -INFINITY};
    float l_i[2] = {0.f, 0.f};
    float o[8][4];
#pragma unroll
    for (int nt = 0; nt < 8; ++nt)
#pragma unroll
        for (int r = 0; r < 4; ++r) o[nt][r] = 0.f;

    for (int kt = 0; kt < 16; ++kt) {
        const uint32_t* Ks = sm + 4608 + (kt & 1) * 4608;
        const uint32_t* Vt = Ks + 2304;

        // S = Q K^T  (warp rows wid*16..+16, 64 keys); scores in log2 domain.
        float s[8][4];
#pragma unroll
        for (int nt = 0; nt < 8; ++nt)
#pragma unroll
            for (int r = 0; r < 4; ++r) s[nt][r] = 0.f;

#pragma unroll
        for (int ks = 0; ks < 4; ++ks) {
            const int kc = ks * 8 + (lane & 3);
#pragma unroll
            for (int nt = 0; nt < 8; ++nt) {
                const int key = nt * 8 + (lane >> 2);
                uint32_t bf[2];
                bf[0] = Ks[key * 36 + kc];
                bf[1] = Ks[key * 36 + kc + 4];
                mma_f16(s[nt], aq[ks], bf);
            }
        }

        // Online softmax, base 2 (lane quad xor 1,2 shares the row).
#pragma unroll
        for (int r = 0; r < 2; ++r) {
            float tm = -INFINITY;
#pragma unroll
            for (int nt = 0; nt < 8; ++nt)
                tm = fmaxf(tm, fmaxf(s[nt][2 * r], s[nt][2 * r + 1]));
            tm = fmaxf(tm, __shfl_xor_sync(0xffffffffu, tm, 1));
            tm = fmaxf(tm, __shfl_xor_sync(0xffffffffu, tm, 2));

            float mn = fmaxf(m_i[r], tm);
            float alpha = ex2(m_i[r] - mn);   // ex2(-inf)=0 first iter
            m_i[r] = mn;

            float ps = 0.f;
#pragma unroll
            for (int nt = 0; nt < 8; ++nt) {
                s[nt][2 * r]     = ex2(s[nt][2 * r] - mn);
                s[nt][2 * r + 1] = ex2(s[nt][2 * r + 1] - mn);
                ps += s[nt][2 * r] + s[nt][2 * r + 1];
            }
            ps += __shfl_xor_sync(0xffffffffu, ps, 1);
            ps += __shfl_xor_sync(0xffffffffu, ps, 2);

            l_i[r] = l_i[r] * alpha + ps;
#pragma unroll
            for (int nt = 0; nt < 8; ++nt) {
                o[nt][2 * r]     *= alpha;
                o[nt][2 * r + 1] *= alpha;
            }
        }

        // O += P V  (P packed straight from registers)
#pragma unroll
        for (int ks = 0; ks < 4; ++ks) {
            uint32_t ap[4];
            ap[0] = pack2h(s[2 * ks][0],     s[2 * ks][1]);
            ap[1] = pack2h(s[2 * ks][2],     s[2 * ks][3]);
            ap[2] = pack2h(s[2 * ks + 1][0], s[2 * ks + 1][1]);
            ap[3] = pack2h(s[2 * ks + 1][2], s[2 * ks + 1][3]);
            const int kc = ks * 8 + (lane & 3);
#pragma unroll
            for (int nt = 0; nt < 8; ++nt) {
                const int dd = nt * 8 + (lane >> 2);
                uint32_t bf[2];
                bf[0] = Vt[dd * 36 + kc];
                bf[1] = Vt[dd * 36 + kc + 4];
                mma_f16(o[nt], ap, bf);
            }
        }

        __syncthreads();                       // done reading buf[kt&1]
        if (kt + 2 < 16) {
            stageKV(kt + 2, kt & 1);
            CP_COMMIT();
        }
        if (kt < 15) {
            if (kt + 2 < 16) CP_WAIT1();
            else             CP_WAIT0();
            __syncthreads();                   // buf[(kt+1)&1] ready
        }
    }

    // Epilogue: normalize, write ctx as fp16 (consumed by o_gemm).
#pragma unroll
    for (int r = 0; r < 2; ++r) {
        const float inv = 1.0f / l_i[r];
        const int row = s0 + wid * 16 + (lane >> 2) + r * 8;
#pragma unroll
        for (int nt = 0; nt < 8; ++nt) {
            const int dd = nt * 8 + (lane & 3) * 2;
            *(uint32_t*)&g_ctxh[baseq + (size_t)row * Csz + dd] =
                pack2h(o[nt][2 * r] * inv, o[nt][2 * r + 1] * inv);
        }
    }
}

// ---------------------------------------------------------------------------
// Launch
// ---------------------------------------------------------------------------
extern "C" void kernel_launch(void* const* d_in, const int* in_sizes, int n_in,
                              void* d_out, int out_size) {
    const float* x    = (const float*)d_in[0];
    const float* skip = (const float*)d_in[1];
    const float* Wq   = (const float*)d_in[2];
    const float* bq   = (const float*)d_in[3];
    const float* Wk   = (const float*)d_in[4];
    const float* bk   = (const float*)d_in[5];
    const float* Wv   = (const float*)d_in[6];
    const float* bv   = (const float*)d_in[7];
    const float* Wo   = (const float*)d_in[8];
    const float* bo   = (const float*)d_in[9];
    float* out = (float*)d_out;

    // Single fused conversion launch
    cvt_all<<<(NCVT4 + 255) / 256, 256>>>(x, Wq, Wk, Wv, Wo);

    cudaFuncSetAttribute(qkv_gemm, cudaFuncAttributeMaxDynamicSharedMemorySize,
                         GEMM_SMEM);
    cudaFuncSetAttribute(o_gemm, cudaFuncAttributeMaxDynamicSharedMemorySize,
                         GEMM_SMEM);
    cudaFuncSetAttribute(attn_tc, cudaFuncAttributeMaxDynamicSharedMemorySize,
                         ATTN_SMEM);

    dim3 qkvgrid(Csz / 128, Mtot / 128, 3);   // (4, 64, 3)
    qkv_gemm<<<qkvgrid, 256, GEMM_SMEM>>>(bq, bk, bv);

    dim3 agrid(Ssz / 128, Hsz, Bsz);          // (8, 8, 8)
    attn_tc<<<agrid, 256, ATTN_SMEM>>>();

    dim3 ogrid(Csz / 128, Mtot / 128);        // (4, 64)
    o_gemm<<<ogrid, 256, GEMM_SMEM>>>(bo, skip, out);
}